// round 13
// baseline (speedup 1.0000x reference)
#include <cuda_runtime.h>
#include <cuda.h>
#include <math.h>

#define B_ 8
#define N_ 65536
#define M_ 8
#define NBLK 64
#define RED_THREADS 256
#define C_THREADS 512
#define TILE_CELLS 512
#define TILE_BYTES (TILE_CELLS * 64)          // 32768
#define TILE_ROWS (TILE_BYTES / 128)          // 256 rows of 128B
#define TOTAL_ROWS (B_ * N_ * 64 / 128)       // 262144
#define APPLY_GRID (B_ * N_ / TILE_CELLS)     // 1024
#define TILES_PER_BATCH (N_ / TILE_CELLS)     // 128

// Scratch (no cudaMalloc allowed)
__device__ float g_partials[B_ * NBLK * 16];          // [b][blk][16]

// ---------------------------------------------------------------------------
// Compile-time Cayley sign for Cl(3,0,1), replicating the reference loop.
// ---------------------------------------------------------------------------
__host__ __device__ constexpr int cpop4(unsigned v) {
    return (int)((v & 1u) + ((v >> 1) & 1u) + ((v >> 2) & 1u) + ((v >> 3) & 1u));
}
__host__ __device__ constexpr float csign(int i, int j) {
    float s = 1.0f;
    for (int b = 0; b < 4; b++) {
        if ((j >> b) & 1) {
            if (cpop4((unsigned)(i >> (b + 1))) & 1) s = -s;
            if ((i >> b) & 1) {
                if (b == 0) s = 0.0f;  // metric[0] = 0
            }
        }
    }
    return s;
}

// SW128 swizzle (matches CU_TENSOR_MAP_SWIZZLE_128B): XOR bits[4:6] w/ bits[7:9]
__device__ __forceinline__ unsigned sw128(unsigned off) {
    return off ^ ((off >> 3) & 0x70u);
}

// ---------------------------------------------------------------------------
// Kernel A: partial sums of cpu_state over N, per batch.
// (round-11 config: NBLK=64, 16 unrolled float4 loads/thread)
// ---------------------------------------------------------------------------
__global__ void gss_reduce_kernel(const float* __restrict__ cpu_state) {
    int b = blockIdx.y;
    const float4* src = (const float4*)(cpu_state + (size_t)b * N_ * 16);
    const int T = NBLK * RED_THREADS;            // 16384 threads per batch
    int t = blockIdx.x * RED_THREADS + threadIdx.x;

    float4 v[16];
#pragma unroll
    for (int k = 0; k < 16; k++) v[k] = __ldcg(src + t + k * T);

    float4 acc = make_float4(0.f, 0.f, 0.f, 0.f);
#pragma unroll
    for (int k = 0; k < 16; k++) {
        acc.x += v[k].x; acc.y += v[k].y; acc.z += v[k].z; acc.w += v[k].w;
    }

    int lane = threadIdx.x & 31;
    int warp = threadIdx.x >> 5;
#pragma unroll
    for (int off = 16; off >= 4; off >>= 1) {
        acc.x += __shfl_xor_sync(0xffffffffu, acc.x, off);
        acc.y += __shfl_xor_sync(0xffffffffu, acc.y, off);
        acc.z += __shfl_xor_sync(0xffffffffu, acc.z, off);
        acc.w += __shfl_xor_sync(0xffffffffu, acc.w, off);
    }
    __shared__ float4 sm[8][4];
    if (lane < 4) sm[warp][lane] = acc;   // lane==q holds quarter q
    __syncthreads();
    if (warp == 0) {
        float4 a2 = sm[lane >> 2][lane & 3];
#pragma unroll
        for (int off = 16; off >= 4; off >>= 1) {
            a2.x += __shfl_xor_sync(0xffffffffu, a2.x, off);
            a2.y += __shfl_xor_sync(0xffffffffu, a2.y, off);
            a2.z += __shfl_xor_sync(0xffffffffu, a2.z, off);
            a2.w += __shfl_xor_sync(0xffffffffu, a2.w, off);
        }
        if (lane < 4) {
            float* dst = g_partials + (b * NBLK + blockIdx.x) * 16 + lane * 4;
            dst[0] = a2.x; dst[1] = a2.y; dst[2] = a2.z; dst[3] = a2.w;
        }
    }
}

// ---------------------------------------------------------------------------
// Threefry-2x32 (JAX partitionable scheme: counter (0, e), bits = o0^o1)
// ---------------------------------------------------------------------------
__device__ __forceinline__ unsigned tf_rotl(unsigned v, int d) {
    return (v << d) | (v >> (32 - d));
}

__device__ void threefry2x32(unsigned k0, unsigned k1,
                             unsigned c0, unsigned c1,
                             unsigned& o0, unsigned& o1) {
    unsigned ks0 = k0, ks1 = k1, ks2 = k0 ^ k1 ^ 0x1BD11BDAu;
    unsigned x0 = c0 + ks0;
    unsigned x1 = c1 + ks1;
    const int r0[4] = {13, 15, 26, 6};
    const int r1[4] = {17, 29, 16, 24};
#define TF_BLOCK(R)                                            \
    {                                                          \
        _Pragma("unroll")                                      \
        for (int q = 0; q < 4; q++) {                          \
            x0 += x1;                                          \
            x1 = tf_rotl(x1, (R)[q]);                          \
            x1 ^= x0;                                          \
        }                                                      \
    }
    TF_BLOCK(r0); x0 += ks1; x1 += ks2 + 1u;
    TF_BLOCK(r1); x0 += ks2; x1 += ks0 + 2u;
    TF_BLOCK(r0); x0 += ks0; x1 += ks1 + 3u;
    TF_BLOCK(r1); x0 += ks1; x1 += ks2 + 4u;
    TF_BLOCK(r0); x0 += ks2; x1 += ks0 + 5u;
#undef TF_BLOCK
    o0 = x0; o1 = x1;
}

// ---------------------------------------------------------------------------
// Kernel C: TMA in (SW128) -> embedded per-batch scoring (overlapped with the
// TMA flight) -> per-thread geometric product in place -> TMA out.
// 512 cells/block, 1 cell/thread, 512 threads (16 warps for latency hiding).
// ---------------------------------------------------------------------------
__global__ void __launch_bounds__(C_THREADS)
gss_apply_kernel(const __grid_constant__ CUtensorMap tmap_in,
                 const __grid_constant__ CUtensorMap tmap_out,
                 const float* __restrict__ ctrl,
                 const float* __restrict__ rule_mem,
                 const float* __restrict__ templates,
                 const float* __restrict__ W1,
                 const float* __restrict__ b1,
                 const float* __restrict__ W2,
                 const float* __restrict__ b2,
                 const float* __restrict__ Wr,
                 const float* __restrict__ br,
                 const float* __restrict__ log_temp) {
    __shared__ __align__(1024) char smt[TILE_BYTES];   // 32 KB tile
    __shared__ __align__(8) unsigned long long mbar;
    // scoring scratch (one batch)
    __shared__ float summ[16];
    __shared__ float si[9];
    __shared__ float hid[64];
    __shared__ float sc[8];
    __shared__ float rs[16];
    __shared__ float rmod[128];
    __shared__ float wts[8];
    __shared__ float combS[16];

    const int tid = threadIdx.x;
    const int lane = tid & 31;
    const int warp = tid >> 5;
    const unsigned smem_tile = (unsigned)__cvta_generic_to_shared(smt);
    const unsigned smem_bar  = (unsigned)__cvta_generic_to_shared(&mbar);
    const int row0 = blockIdx.x * TILE_ROWS;
    const int b = blockIdx.x / TILES_PER_BATCH;

    if (tid == 0) {
        asm volatile("mbarrier.init.shared.b64 [%0], %1;"
                     :: "r"(smem_bar), "r"(1) : "memory");
    }
    __syncthreads();
    if (tid == 0) {
        asm volatile("mbarrier.arrive.expect_tx.shared.b64 _, [%0], %1;"
                     :: "r"(smem_bar), "r"(TILE_BYTES) : "memory");
        asm volatile(
            "cp.async.bulk.tensor.2d.shared::cta.global.tile.mbarrier::complete_tx::bytes "
            "[%0], [%1, {%2, %3}], [%4];"
            :: "r"(smem_tile), "l"(&tmap_in), "r"(0), "r"(row0), "r"(smem_bar)
            : "memory");
    }

    // ---- scoring for batch b, overlapped with the TMA flight ----
    if (warp == 0) {
        // chain 1: cpu summary -> norms -> MLP -> scores -> gumbel -> softmax
        if (lane < 16) {
            float s = 0.f;
#pragma unroll 8
            for (int blk = 0; blk < NBLK; blk++)
                s += g_partials[(b * NBLK + blk) * 16 + lane];
            summ[lane] = s * (1.0f / N_);
        }
        __syncwarp();
        if (lane < 5) {
            float s = 0.f;
            for (int d = 0; d < 16; d++)
                if (__popc(d) == lane) { float v = summ[d]; s += v * v; }
            si[lane] = sqrtf(s + 1e-12f);
        }
        if (lane >= 5 && lane < 9) si[lane] = ctrl[b * 4 + (lane - 5)];
        __syncwarp();
        for (int h = lane; h < 64; h += 32) {
            float a = b1[h];
#pragma unroll
            for (int i = 0; i < 9; i++) a += si[i] * W1[i * 64 + h];
            hid[h] = fmaxf(a, 0.f);
        }
        __syncwarp();
        if (lane < 8) {
            float a = b2[lane];
            for (int h = 0; h < 64; h++) a += hid[h] * W2[h * 8 + lane];
            sc[lane] = a;
        }
        __syncwarp();
        if (lane < 8) {
            int e = b * 8 + lane;
            unsigned o0, o1;
            threefry2x32(0u, 42u, 0u, (unsigned)e, o0, o1);
            unsigned bits = o0 ^ o1;
            float u = __uint_as_float((bits >> 9) | 0x3f800000u) - 1.0f;
            const float minv = 1e-6f, maxv = 1.0f - 1e-6f;
            u = fmaxf(minv, u * (maxv - minv) + minv);
            float g = -logf(-logf(u));
            float tau = fminf(fmaxf(expf(log_temp[0]), 0.1f), 5.0f);
            wts[lane] = (sc[lane] + g) / tau;
        }
        __syncwarp();
        if (lane == 0) {
            float mx = -1e30f;
            for (int k = 0; k < 8; k++) mx = fmaxf(mx, wts[k]);
            float s = 0.f;
            for (int k = 0; k < 8; k++) { float e = expf(wts[k] - mx); wts[k] = e; s += e; }
            float inv = 1.0f / s;
            for (int k = 0; k < 8; k++) wts[k] *= inv;
        }
    } else if (warp == 1) {
        // chain 2 (independent): rule summary -> rule mod
        if (lane < 16) {
            float s = 0.f;
            for (int m = 0; m < M_; m++) s += rule_mem[(b * M_ + m) * 16 + lane];
            rs[lane] = s * (1.0f / M_);
        }
        __syncwarp();
        for (int j = lane; j < 128; j += 32) {
            float a = br[j];
#pragma unroll
            for (int d = 0; d < 16; d++) a += rs[d] * Wr[d * 128 + j];
            rmod[j] = a;
        }
    }
    __syncthreads();     // both chains done
    if (warp == 0 && lane < 16) {
        float s = 0.f;
#pragma unroll
        for (int k = 0; k < 8; k++)
            s += wts[k] * sc[k] * (templates[k * 16 + lane] + rmod[k * 16 + lane]);
        combS[lane] = s;
    }
    __syncthreads();     // combS visible

    // wait for TMA load (parity 0)
    asm volatile(
        "{\n\t.reg .pred P;\n"
        "W_%=:\n\t"
        "mbarrier.try_wait.parity.acquire.cta.shared::cta.b64 P, [%0], %1, 0x989680;\n\t"
        "@P bra D_%=;\n\t"
        "bra W_%=;\n"
        "D_%=:\n\t}"
        :: "r"(smem_bar), "r"(0) : "memory");

    float a[16];
#pragma unroll
    for (int j = 0; j < 16; j++) a[j] = combS[j];

    // 1 cell per thread (same-thread slots: no sync between read and write)
    {
        int cc = tid;
        float x[16];
#pragma unroll
        for (int q = 0; q < 4; q++) {
            unsigned off = (unsigned)cc * 64u + (unsigned)q * 16u;
            float4 v = *(const float4*)(smt + sw128(off));
            x[q * 4 + 0] = v.x; x[q * 4 + 1] = v.y;
            x[q * 4 + 2] = v.z; x[q * 4 + 3] = v.w;
        }
        float y[16];
#pragma unroll
        for (int l = 0; l < 16; l++) {
            float s = 0.f;
#pragma unroll
            for (int j = 0; j < 16; j++) {
                const float sgn = csign(j ^ l, j);   // compile-time constant
                if (sgn > 0.5f)       s = fmaf(a[j ^ l],  x[j], s);
                else if (sgn < -0.5f) s = fmaf(-a[j ^ l], x[j], s);
            }
            y[l] = s;
        }
#pragma unroll
        for (int q = 0; q < 4; q++) {
            unsigned off = (unsigned)cc * 64u + (unsigned)q * 16u;
            *(float4*)(smt + sw128(off)) =
                make_float4(y[q * 4 + 0], y[q * 4 + 1], y[q * 4 + 2], y[q * 4 + 3]);
        }
    }

    asm volatile("fence.proxy.async.shared::cta;" ::: "memory");
    __syncthreads();

    if (tid == 0) {
        asm volatile(
            "cp.async.bulk.tensor.2d.global.shared::cta.tile.bulk_group "
            "[%0, {%1, %2}], [%3];"
            :: "l"(&tmap_out), "r"(0), "r"(row0), "r"(smem_tile) : "memory");
        asm volatile("cp.async.bulk.commit_group;" ::: "memory");
        asm volatile("cp.async.bulk.wait_group 0;" ::: "memory");
    }
}

// ---------------------------------------------------------------------------
// Host: tensor map encode via driver entry point (no -lcuda needed)
// ---------------------------------------------------------------------------
typedef CUresult (*PFN_encodeTiled)(
    CUtensorMap*, CUtensorMapDataType, cuuint32_t, void*,
    const cuuint64_t*, const cuuint64_t*, const cuuint32_t*, const cuuint32_t*,
    CUtensorMapInterleave, CUtensorMapSwizzle, CUtensorMapL2promotion,
    CUtensorMapFloatOOBfill);

static void make_tmap(CUtensorMap* map, void* ptr) {
    static PFN_encodeTiled fn = nullptr;
    if (!fn) {
        cudaDriverEntryPointQueryResult qres;
        void* p = nullptr;
        cudaGetDriverEntryPoint("cuTensorMapEncodeTiled", &p,
                                cudaEnableDefault, &qres);
        fn = (PFN_encodeTiled)p;
    }
    cuuint64_t dims[2]    = {32, (cuuint64_t)TOTAL_ROWS};  // 32 f32 = 128B rows
    cuuint64_t strides[1] = {128};
    cuuint32_t box[2]     = {32, TILE_ROWS};
    cuuint32_t estr[2]    = {1, 1};
    fn(map, CU_TENSOR_MAP_DATA_TYPE_FLOAT32, 2, ptr, dims, strides, box, estr,
       CU_TENSOR_MAP_INTERLEAVE_NONE, CU_TENSOR_MAP_SWIZZLE_128B,
       CU_TENSOR_MAP_L2_PROMOTION_L2_128B, CU_TENSOR_MAP_FLOAT_OOB_FILL_NONE);
}

extern "C" void kernel_launch(void* const* d_in, const int* in_sizes, int n_in,
                              void* d_out, int out_size) {
    const float* cpu_state   = (const float*)d_in[0];
    const float* ctrl_cursor = (const float*)d_in[1];
    const float* rule_memory = (const float*)d_in[2];
    const float* templates   = (const float*)d_in[3];
    const float* W1          = (const float*)d_in[4];
    const float* b1          = (const float*)d_in[5];
    const float* W2          = (const float*)d_in[6];
    const float* b2          = (const float*)d_in[7];
    const float* Wr          = (const float*)d_in[8];
    const float* br          = (const float*)d_in[9];
    const float* log_temp    = (const float*)d_in[10];

    CUtensorMap tmap_in, tmap_out;
    make_tmap(&tmap_in, (void*)cpu_state);
    make_tmap(&tmap_out, d_out);

    dim3 gA(NBLK, B_);
    gss_reduce_kernel<<<gA, RED_THREADS>>>(cpu_state);

    gss_apply_kernel<<<APPLY_GRID, C_THREADS>>>(
        tmap_in, tmap_out, ctrl_cursor, rule_memory, templates,
        W1, b1, W2, b2, Wr, br, log_temp);
}

// round 14
// speedup vs baseline: 1.4286x; 1.4286x over previous
#include <cuda_runtime.h>
#include <cuda.h>
#include <math.h>

#define B_ 8
#define N_ 65536
#define M_ 8
#define NBLK 64
#define RED_THREADS 256
#define C_THREADS 256
#define TILE_CELLS 512
#define TILE_BYTES (TILE_CELLS * 64)          // 32768
#define TILE_ROWS (TILE_BYTES / 128)          // 256 rows of 128B
#define TOTAL_ROWS (B_ * N_ * 64 / 128)       // 262144
#define APPLY_GRID (B_ * N_ / TILE_CELLS)     // 1024
#define TILES_PER_BATCH (N_ / TILE_CELLS)     // 128

// Scratch (no cudaMalloc allowed)
__device__ float g_partials[B_ * NBLK * 16];          // [b][blk][16]

// ---------------------------------------------------------------------------
// Compile-time Cayley sign for Cl(3,0,1), replicating the reference loop.
// ---------------------------------------------------------------------------
__host__ __device__ constexpr int cpop4(unsigned v) {
    return (int)((v & 1u) + ((v >> 1) & 1u) + ((v >> 2) & 1u) + ((v >> 3) & 1u));
}
__host__ __device__ constexpr float csign(int i, int j) {
    float s = 1.0f;
    for (int b = 0; b < 4; b++) {
        if ((j >> b) & 1) {
            if (cpop4((unsigned)(i >> (b + 1))) & 1) s = -s;
            if ((i >> b) & 1) {
                if (b == 0) s = 0.0f;  // metric[0] = 0
            }
        }
    }
    return s;
}

// SW128 swizzle (matches CU_TENSOR_MAP_SWIZZLE_128B): XOR bits[4:6] w/ bits[7:9]
__device__ __forceinline__ unsigned sw128(unsigned off) {
    return off ^ ((off >> 3) & 0x70u);
}

// ---------------------------------------------------------------------------
// Kernel A: partial sums of cpu_state over N, per batch.
// (round-11 config: NBLK=64, 16 unrolled float4 loads/thread) + PDL trigger.
// ---------------------------------------------------------------------------
__global__ void gss_reduce_kernel(const float* __restrict__ cpu_state) {
    int b = blockIdx.y;
    const float4* src = (const float4*)(cpu_state + (size_t)b * N_ * 16);
    const int T = NBLK * RED_THREADS;            // 16384 threads per batch
    int t = blockIdx.x * RED_THREADS + threadIdx.x;

    float4 v[16];
#pragma unroll
    for (int k = 0; k < 16; k++) v[k] = __ldcg(src + t + k * T);

    float4 acc = make_float4(0.f, 0.f, 0.f, 0.f);
#pragma unroll
    for (int k = 0; k < 16; k++) {
        acc.x += v[k].x; acc.y += v[k].y; acc.z += v[k].z; acc.w += v[k].w;
    }

    int lane = threadIdx.x & 31;
    int warp = threadIdx.x >> 5;
#pragma unroll
    for (int off = 16; off >= 4; off >>= 1) {
        acc.x += __shfl_xor_sync(0xffffffffu, acc.x, off);
        acc.y += __shfl_xor_sync(0xffffffffu, acc.y, off);
        acc.z += __shfl_xor_sync(0xffffffffu, acc.z, off);
        acc.w += __shfl_xor_sync(0xffffffffu, acc.w, off);
    }
    __shared__ float4 sm[8][4];
    if (lane < 4) sm[warp][lane] = acc;   // lane==q holds quarter q
    __syncthreads();
    if (warp == 0) {
        float4 a2 = sm[lane >> 2][lane & 3];
#pragma unroll
        for (int off = 16; off >= 4; off >>= 1) {
            a2.x += __shfl_xor_sync(0xffffffffu, a2.x, off);
            a2.y += __shfl_xor_sync(0xffffffffu, a2.y, off);
            a2.z += __shfl_xor_sync(0xffffffffu, a2.z, off);
            a2.w += __shfl_xor_sync(0xffffffffu, a2.w, off);
        }
        if (lane < 4) {
            float* dst = g_partials + (b * NBLK + blockIdx.x) * 16 + lane * 4;
            dst[0] = a2.x; dst[1] = a2.y; dst[2] = a2.z; dst[3] = a2.w;
        }
    }
    __syncthreads();   // g_partials store issued before any thread triggers
    cudaTriggerProgrammaticLaunchCompletion();
}

// ---------------------------------------------------------------------------
// Threefry-2x32 (JAX partitionable scheme: counter (0, e), bits = o0^o1)
// ---------------------------------------------------------------------------
__device__ __forceinline__ unsigned tf_rotl(unsigned v, int d) {
    return (v << d) | (v >> (32 - d));
}

__device__ void threefry2x32(unsigned k0, unsigned k1,
                             unsigned c0, unsigned c1,
                             unsigned& o0, unsigned& o1) {
    unsigned ks0 = k0, ks1 = k1, ks2 = k0 ^ k1 ^ 0x1BD11BDAu;
    unsigned x0 = c0 + ks0;
    unsigned x1 = c1 + ks1;
    const int r0[4] = {13, 15, 26, 6};
    const int r1[4] = {17, 29, 16, 24};
#define TF_BLOCK(R)                                            \
    {                                                          \
        _Pragma("unroll")                                      \
        for (int q = 0; q < 4; q++) {                          \
            x0 += x1;                                          \
            x1 = tf_rotl(x1, (R)[q]);                          \
            x1 ^= x0;                                          \
        }                                                      \
    }
    TF_BLOCK(r0); x0 += ks1; x1 += ks2 + 1u;
    TF_BLOCK(r1); x0 += ks2; x1 += ks0 + 2u;
    TF_BLOCK(r0); x0 += ks0; x1 += ks1 + 3u;
    TF_BLOCK(r1); x0 += ks1; x1 += ks2 + 4u;
    TF_BLOCK(r0); x0 += ks2; x1 += ks0 + 5u;
#undef TF_BLOCK
    o0 = x0; o1 = x1;
}

// ---------------------------------------------------------------------------
// Kernel C (round-11 validated geometry): TMA in -> grid-dep-sync -> embedded
// scoring -> per-thread geometric product in place -> TMA out.
// 512 cells/block, 256 threads, 2 cells/thread.
// ---------------------------------------------------------------------------
__global__ void __launch_bounds__(C_THREADS)
gss_apply_kernel(const __grid_constant__ CUtensorMap tmap_in,
                 const __grid_constant__ CUtensorMap tmap_out,
                 const float* __restrict__ ctrl,
                 const float* __restrict__ rule_mem,
                 const float* __restrict__ templates,
                 const float* __restrict__ W1,
                 const float* __restrict__ b1,
                 const float* __restrict__ W2,
                 const float* __restrict__ b2,
                 const float* __restrict__ Wr,
                 const float* __restrict__ br,
                 const float* __restrict__ log_temp) {
    __shared__ __align__(1024) char smt[TILE_BYTES];   // 32 KB tile
    __shared__ __align__(8) unsigned long long mbar;
    // scoring scratch (one batch)
    __shared__ float summ[16];
    __shared__ float si[9];
    __shared__ float hid[64];
    __shared__ float sc[8];
    __shared__ float rs[16];
    __shared__ float rmod[128];
    __shared__ float wts[8];
    __shared__ float combS[16];

    const int tid = threadIdx.x;
    const int lane = tid & 31;
    const int warp = tid >> 5;
    const unsigned smem_tile = (unsigned)__cvta_generic_to_shared(smt);
    const unsigned smem_bar  = (unsigned)__cvta_generic_to_shared(&mbar);
    const int row0 = blockIdx.x * TILE_ROWS;
    const int b = blockIdx.x / TILES_PER_BATCH;

    if (tid == 0) {
        asm volatile("mbarrier.init.shared.b64 [%0], %1;"
                     :: "r"(smem_bar), "r"(1) : "memory");
    }
    __syncthreads();
    if (tid == 0) {
        asm volatile("mbarrier.arrive.expect_tx.shared.b64 _, [%0], %1;"
                     :: "r"(smem_bar), "r"(TILE_BYTES) : "memory");
        asm volatile(
            "cp.async.bulk.tensor.2d.shared::cta.global.tile.mbarrier::complete_tx::bytes "
            "[%0], [%1, {%2, %3}], [%4];"
            :: "r"(smem_tile), "l"(&tmap_in), "r"(0), "r"(row0), "r"(smem_bar)
            : "memory");
    }

    // PDL: wait for the reduce grid's g_partials to be visible.
    // (TMA load above is independent of the reduce and already in flight.)
    cudaGridDependencySynchronize();

    // ---- scoring for batch b, overlapped with the TMA flight ----
    if (warp == 0) {
        // chain 1: cpu summary -> norms -> MLP -> scores -> gumbel -> softmax
        if (lane < 16) {
            float s = 0.f;
#pragma unroll 8
            for (int blk = 0; blk < NBLK; blk++)
                s += g_partials[(b * NBLK + blk) * 16 + lane];
            summ[lane] = s * (1.0f / N_);
        }
        __syncwarp();
        if (lane < 5) {
            float s = 0.f;
            for (int d = 0; d < 16; d++)
                if (__popc(d) == lane) { float v = summ[d]; s += v * v; }
            si[lane] = sqrtf(s + 1e-12f);
        }
        if (lane >= 5 && lane < 9) si[lane] = ctrl[b * 4 + (lane - 5)];
        __syncwarp();
        for (int h = lane; h < 64; h += 32) {
            float a = b1[h];
#pragma unroll
            for (int i = 0; i < 9; i++) a += si[i] * W1[i * 64 + h];
            hid[h] = fmaxf(a, 0.f);
        }
        __syncwarp();
        if (lane < 8) {
            float a = b2[lane];
            for (int h = 0; h < 64; h++) a += hid[h] * W2[h * 8 + lane];
            sc[lane] = a;
        }
        __syncwarp();
        if (lane < 8) {
            int e = b * 8 + lane;
            unsigned o0, o1;
            threefry2x32(0u, 42u, 0u, (unsigned)e, o0, o1);
            unsigned bits = o0 ^ o1;
            float u = __uint_as_float((bits >> 9) | 0x3f800000u) - 1.0f;
            const float minv = 1e-6f, maxv = 1.0f - 1e-6f;
            u = fmaxf(minv, u * (maxv - minv) + minv);
            float g = -logf(-logf(u));
            float tau = fminf(fmaxf(expf(log_temp[0]), 0.1f), 5.0f);
            wts[lane] = (sc[lane] + g) / tau;
        }
        __syncwarp();
        if (lane == 0) {
            float mx = -1e30f;
            for (int k = 0; k < 8; k++) mx = fmaxf(mx, wts[k]);
            float s = 0.f;
            for (int k = 0; k < 8; k++) { float e = expf(wts[k] - mx); wts[k] = e; s += e; }
            float inv = 1.0f / s;
            for (int k = 0; k < 8; k++) wts[k] *= inv;
        }
    } else if (warp == 1) {
        // chain 2 (independent): rule summary -> rule mod
        if (lane < 16) {
            float s = 0.f;
            for (int m = 0; m < M_; m++) s += rule_mem[(b * M_ + m) * 16 + lane];
            rs[lane] = s * (1.0f / M_);
        }
        __syncwarp();
        for (int j = lane; j < 128; j += 32) {
            float a = br[j];
#pragma unroll
            for (int d = 0; d < 16; d++) a += rs[d] * Wr[d * 128 + j];
            rmod[j] = a;
        }
    }
    __syncthreads();     // both chains done
    if (warp == 0 && lane < 16) {
        float s = 0.f;
#pragma unroll
        for (int k = 0; k < 8; k++)
            s += wts[k] * sc[k] * (templates[k * 16 + lane] + rmod[k * 16 + lane]);
        combS[lane] = s;
    }
    __syncthreads();     // combS visible

    // wait for TMA load (parity 0)
    asm volatile(
        "{\n\t.reg .pred P;\n"
        "W_%=:\n\t"
        "mbarrier.try_wait.parity.acquire.cta.shared::cta.b64 P, [%0], %1, 0x989680;\n\t"
        "@P bra D_%=;\n\t"
        "bra W_%=;\n"
        "D_%=:\n\t}"
        :: "r"(smem_bar), "r"(0) : "memory");

    float a[16];
#pragma unroll
    for (int j = 0; j < 16; j++) a[j] = combS[j];

    // 2 cells per thread, processed sequentially (same-thread slots: no sync)
#pragma unroll
    for (int half = 0; half < 2; half++) {
        int cc = tid + half * C_THREADS;
        float x[16];
#pragma unroll
        for (int q = 0; q < 4; q++) {
            unsigned off = (unsigned)cc * 64u + (unsigned)q * 16u;
            float4 v = *(const float4*)(smt + sw128(off));
            x[q * 4 + 0] = v.x; x[q * 4 + 1] = v.y;
            x[q * 4 + 2] = v.z; x[q * 4 + 3] = v.w;
        }
        float y[16];
#pragma unroll
        for (int l = 0; l < 16; l++) {
            float s = 0.f;
#pragma unroll
            for (int j = 0; j < 16; j++) {
                const float sgn = csign(j ^ l, j);   // compile-time constant
                if (sgn > 0.5f)       s = fmaf(a[j ^ l],  x[j], s);
                else if (sgn < -0.5f) s = fmaf(-a[j ^ l], x[j], s);
            }
            y[l] = s;
        }
#pragma unroll
        for (int q = 0; q < 4; q++) {
            unsigned off = (unsigned)cc * 64u + (unsigned)q * 16u;
            *(float4*)(smt + sw128(off)) =
                make_float4(y[q * 4 + 0], y[q * 4 + 1], y[q * 4 + 2], y[q * 4 + 3]);
        }
    }

    asm volatile("fence.proxy.async.shared::cta;" ::: "memory");
    __syncthreads();

    if (tid == 0) {
        asm volatile(
            "cp.async.bulk.tensor.2d.global.shared::cta.tile.bulk_group "
            "[%0, {%1, %2}], [%3];"
            :: "l"(&tmap_out), "r"(0), "r"(row0), "r"(smem_tile) : "memory");
        asm volatile("cp.async.bulk.commit_group;" ::: "memory");
        asm volatile("cp.async.bulk.wait_group 0;" ::: "memory");
    }
}

// ---------------------------------------------------------------------------
// Host: tensor map encode via driver entry point (no -lcuda needed)
// ---------------------------------------------------------------------------
typedef CUresult (*PFN_encodeTiled)(
    CUtensorMap*, CUtensorMapDataType, cuuint32_t, void*,
    const cuuint64_t*, const cuuint64_t*, const cuuint32_t*, const cuuint32_t*,
    CUtensorMapInterleave, CUtensorMapSwizzle, CUtensorMapL2promotion,
    CUtensorMapFloatOOBfill);

static void make_tmap(CUtensorMap* map, void* ptr) {
    static PFN_encodeTiled fn = nullptr;
    if (!fn) {
        cudaDriverEntryPointQueryResult qres;
        void* p = nullptr;
        cudaGetDriverEntryPoint("cuTensorMapEncodeTiled", &p,
                                cudaEnableDefault, &qres);
        fn = (PFN_encodeTiled)p;
    }
    cuuint64_t dims[2]    = {32, (cuuint64_t)TOTAL_ROWS};  // 32 f32 = 128B rows
    cuuint64_t strides[1] = {128};
    cuuint32_t box[2]     = {32, TILE_ROWS};
    cuuint32_t estr[2]    = {1, 1};
    fn(map, CU_TENSOR_MAP_DATA_TYPE_FLOAT32, 2, ptr, dims, strides, box, estr,
       CU_TENSOR_MAP_INTERLEAVE_NONE, CU_TENSOR_MAP_SWIZZLE_128B,
       CU_TENSOR_MAP_L2_PROMOTION_L2_128B, CU_TENSOR_MAP_FLOAT_OOB_FILL_NONE);
}

extern "C" void kernel_launch(void* const* d_in, const int* in_sizes, int n_in,
                              void* d_out, int out_size) {
    const float* cpu_state   = (const float*)d_in[0];
    const float* ctrl_cursor = (const float*)d_in[1];
    const float* rule_memory = (const float*)d_in[2];
    const float* templates   = (const float*)d_in[3];
    const float* W1          = (const float*)d_in[4];
    const float* b1          = (const float*)d_in[5];
    const float* W2          = (const float*)d_in[6];
    const float* b2          = (const float*)d_in[7];
    const float* Wr          = (const float*)d_in[8];
    const float* br          = (const float*)d_in[9];
    const float* log_temp    = (const float*)d_in[10];

    CUtensorMap tmap_in, tmap_out;
    make_tmap(&tmap_in, (void*)cpu_state);
    make_tmap(&tmap_out, d_out);

    dim3 gA(NBLK, B_);
    gss_reduce_kernel<<<gA, RED_THREADS>>>(cpu_state);

    // Apply launched with Programmatic Dependent Launch: its prologue (mbarrier
    // init + TMA tile load) overlaps the reduce tail; scoring waits on
    // cudaGridDependencySynchronize().
    cudaLaunchConfig_t cfg = {};
    cfg.gridDim = dim3(APPLY_GRID, 1, 1);
    cfg.blockDim = dim3(C_THREADS, 1, 1);
    cudaLaunchAttribute attrs[1];
    attrs[0].id = cudaLaunchAttributeProgrammaticStreamSerialization;
    attrs[0].val.programmaticStreamSerializationAllowed = 1;
    cfg.attrs = attrs;
    cfg.numAttrs = 1;

    cudaLaunchKernelEx(&cfg, gss_apply_kernel,
                       tmap_in, tmap_out, ctrl_cursor, rule_memory, templates,
                       W1, b1, W2, b2, Wr, br, log_temp);
}

// round 15
// speedup vs baseline: 1.7597x; 1.2318x over previous
#include <cuda_runtime.h>
#include <cuda.h>
#include <math.h>

#define B_ 8
#define N_ 65536
#define M_ 8
#define NBLK 64
#define RED_THREADS 256
#define C_THREADS 256
#define TILE_CELLS 256
#define TILE_BYTES (TILE_CELLS * 64)          // 16384
#define TILE_ROWS (TILE_BYTES / 128)          // 128 rows of 128B
#define TILES_PER_BLOCK 4
#define APPLY_GRID 512                         // single wave (< 740 capacity)
#define BLOCKS_PER_BATCH (APPLY_GRID / B_)     // 64
#define TOTAL_ROWS (B_ * N_ * 64 / 128)        // 262144

// Scratch (no cudaMalloc allowed)
__device__ float g_partials[B_ * NBLK * 16];          // [b][blk][16]

// ---------------------------------------------------------------------------
// Compile-time Cayley sign for Cl(3,0,1), replicating the reference loop.
// ---------------------------------------------------------------------------
__host__ __device__ constexpr int cpop4(unsigned v) {
    return (int)((v & 1u) + ((v >> 1) & 1u) + ((v >> 2) & 1u) + ((v >> 3) & 1u));
}
__host__ __device__ constexpr float csign(int i, int j) {
    float s = 1.0f;
    for (int b = 0; b < 4; b++) {
        if ((j >> b) & 1) {
            if (cpop4((unsigned)(i >> (b + 1))) & 1) s = -s;
            if ((i >> b) & 1) {
                if (b == 0) s = 0.0f;  // metric[0] = 0
            }
        }
    }
    return s;
}

// SW128 swizzle (matches CU_TENSOR_MAP_SWIZZLE_128B): XOR bits[4:6] w/ bits[7:9]
__device__ __forceinline__ unsigned sw128(unsigned off) {
    return off ^ ((off >> 3) & 0x70u);
}

// ---------------------------------------------------------------------------
// Kernel A: partial sums of cpu_state over N, per batch.
// (round-11 config: NBLK=64, 16 unrolled float4 loads/thread)
// ---------------------------------------------------------------------------
__global__ void gss_reduce_kernel(const float* __restrict__ cpu_state) {
    int b = blockIdx.y;
    const float4* src = (const float4*)(cpu_state + (size_t)b * N_ * 16);
    const int T = NBLK * RED_THREADS;            // 16384 threads per batch
    int t = blockIdx.x * RED_THREADS + threadIdx.x;

    float4 v[16];
#pragma unroll
    for (int k = 0; k < 16; k++) v[k] = __ldcg(src + t + k * T);

    float4 acc = make_float4(0.f, 0.f, 0.f, 0.f);
#pragma unroll
    for (int k = 0; k < 16; k++) {
        acc.x += v[k].x; acc.y += v[k].y; acc.z += v[k].z; acc.w += v[k].w;
    }

    int lane = threadIdx.x & 31;
    int warp = threadIdx.x >> 5;
#pragma unroll
    for (int off = 16; off >= 4; off >>= 1) {
        acc.x += __shfl_xor_sync(0xffffffffu, acc.x, off);
        acc.y += __shfl_xor_sync(0xffffffffu, acc.y, off);
        acc.z += __shfl_xor_sync(0xffffffffu, acc.z, off);
        acc.w += __shfl_xor_sync(0xffffffffu, acc.w, off);
    }
    __shared__ float4 sm[8][4];
    if (lane < 4) sm[warp][lane] = acc;   // lane==q holds quarter q
    __syncthreads();
    if (warp == 0) {
        float4 a2 = sm[lane >> 2][lane & 3];
#pragma unroll
        for (int off = 16; off >= 4; off >>= 1) {
            a2.x += __shfl_xor_sync(0xffffffffu, a2.x, off);
            a2.y += __shfl_xor_sync(0xffffffffu, a2.y, off);
            a2.z += __shfl_xor_sync(0xffffffffu, a2.z, off);
            a2.w += __shfl_xor_sync(0xffffffffu, a2.w, off);
        }
        if (lane < 4) {
            float* dst = g_partials + (b * NBLK + blockIdx.x) * 16 + lane * 4;
            dst[0] = a2.x; dst[1] = a2.y; dst[2] = a2.z; dst[3] = a2.w;
        }
    }
}

// ---------------------------------------------------------------------------
// Threefry-2x32 (JAX partitionable scheme: counter (0, e), bits = o0^o1)
// ---------------------------------------------------------------------------
__device__ __forceinline__ unsigned tf_rotl(unsigned v, int d) {
    return (v << d) | (v >> (32 - d));
}

__device__ void threefry2x32(unsigned k0, unsigned k1,
                             unsigned c0, unsigned c1,
                             unsigned& o0, unsigned& o1) {
    unsigned ks0 = k0, ks1 = k1, ks2 = k0 ^ k1 ^ 0x1BD11BDAu;
    unsigned x0 = c0 + ks0;
    unsigned x1 = c1 + ks1;
    const int r0[4] = {13, 15, 26, 6};
    const int r1[4] = {17, 29, 16, 24};
#define TF_BLOCK(R)                                            \
    {                                                          \
        _Pragma("unroll")                                      \
        for (int q = 0; q < 4; q++) {                          \
            x0 += x1;                                          \
            x1 = tf_rotl(x1, (R)[q]);                          \
            x1 ^= x0;                                          \
        }                                                      \
    }
    TF_BLOCK(r0); x0 += ks1; x1 += ks2 + 1u;
    TF_BLOCK(r1); x0 += ks2; x1 += ks0 + 2u;
    TF_BLOCK(r0); x0 += ks0; x1 += ks1 + 3u;
    TF_BLOCK(r1); x0 += ks1; x1 += ks2 + 4u;
    TF_BLOCK(r0); x0 += ks2; x1 += ks0 + 5u;
#undef TF_BLOCK
    o0 = x0; o1 = x1;
}

// ---------------------------------------------------------------------------
// Kernel C: persistent single-wave apply. Each block: 4 contiguous 16KB tiles
// (all in one batch), double-buffered TMA in/out, scoring once per block
// overlapped with the first loads.
// ---------------------------------------------------------------------------
__global__ void __launch_bounds__(C_THREADS)
gss_apply_kernel(const __grid_constant__ CUtensorMap tmap_in,
                 const __grid_constant__ CUtensorMap tmap_out,
                 const float* __restrict__ ctrl,
                 const float* __restrict__ rule_mem,
                 const float* __restrict__ templates,
                 const float* __restrict__ W1,
                 const float* __restrict__ b1,
                 const float* __restrict__ W2,
                 const float* __restrict__ b2,
                 const float* __restrict__ Wr,
                 const float* __restrict__ br,
                 const float* __restrict__ log_temp) {
    __shared__ __align__(1024) char smt[2][TILE_BYTES];   // 2 x 16 KB buffers
    __shared__ __align__(8) unsigned long long mbar[2];
    // scoring scratch (one batch)
    __shared__ float summ[16];
    __shared__ float si[9];
    __shared__ float hid[64];
    __shared__ float sc[8];
    __shared__ float rs[16];
    __shared__ float rmod[128];
    __shared__ float wts[8];
    __shared__ float combS[16];

    const int tid = threadIdx.x;
    const int lane = tid & 31;
    const int warp = tid >> 5;
    const unsigned smem_buf0 = (unsigned)__cvta_generic_to_shared(smt[0]);
    const unsigned smem_buf1 = (unsigned)__cvta_generic_to_shared(smt[1]);
    const unsigned smem_bar0 = (unsigned)__cvta_generic_to_shared(&mbar[0]);
    const unsigned smem_bar1 = (unsigned)__cvta_generic_to_shared(&mbar[1]);
    const int rowBase = blockIdx.x * (TILES_PER_BLOCK * TILE_ROWS);
    const int b = blockIdx.x / BLOCKS_PER_BATCH;

    if (tid == 0) {
        asm volatile("mbarrier.init.shared.b64 [%0], %1;"
                     :: "r"(smem_bar0), "r"(1) : "memory");
        asm volatile("mbarrier.init.shared.b64 [%0], %1;"
                     :: "r"(smem_bar1), "r"(1) : "memory");
    }
    __syncthreads();
    if (tid == 0) {
        // prime the pipeline: tiles 0 and 1
        asm volatile("mbarrier.arrive.expect_tx.shared.b64 _, [%0], %1;"
                     :: "r"(smem_bar0), "r"(TILE_BYTES) : "memory");
        asm volatile(
            "cp.async.bulk.tensor.2d.shared::cta.global.tile.mbarrier::complete_tx::bytes "
            "[%0], [%1, {%2, %3}], [%4];"
            :: "r"(smem_buf0), "l"(&tmap_in), "r"(0), "r"(rowBase), "r"(smem_bar0)
            : "memory");
        asm volatile("mbarrier.arrive.expect_tx.shared.b64 _, [%0], %1;"
                     :: "r"(smem_bar1), "r"(TILE_BYTES) : "memory");
        asm volatile(
            "cp.async.bulk.tensor.2d.shared::cta.global.tile.mbarrier::complete_tx::bytes "
            "[%0], [%1, {%2, %3}], [%4];"
            :: "r"(smem_buf1), "l"(&tmap_in), "r"(0), "r"(rowBase + TILE_ROWS),
               "r"(smem_bar1)
            : "memory");
    }

    // ---- scoring for batch b, overlapped with the TMA flights ----
    if (warp == 0) {
        if (lane < 16) {
            float s = 0.f;
#pragma unroll 8
            for (int blk = 0; blk < NBLK; blk++)
                s += g_partials[(b * NBLK + blk) * 16 + lane];
            summ[lane] = s * (1.0f / N_);
        }
        __syncwarp();
        if (lane < 5) {
            float s = 0.f;
            for (int d = 0; d < 16; d++)
                if (__popc(d) == lane) { float v = summ[d]; s += v * v; }
            si[lane] = sqrtf(s + 1e-12f);
        }
        if (lane >= 5 && lane < 9) si[lane] = ctrl[b * 4 + (lane - 5)];
        __syncwarp();
        for (int h = lane; h < 64; h += 32) {
            float a = b1[h];
#pragma unroll
            for (int i = 0; i < 9; i++) a += si[i] * W1[i * 64 + h];
            hid[h] = fmaxf(a, 0.f);
        }
        __syncwarp();
        if (lane < 8) {
            float a = b2[lane];
            for (int h = 0; h < 64; h++) a += hid[h] * W2[h * 8 + lane];
            sc[lane] = a;
        }
        __syncwarp();
        if (lane < 8) {
            int e = b * 8 + lane;
            unsigned o0, o1;
            threefry2x32(0u, 42u, 0u, (unsigned)e, o0, o1);
            unsigned bits = o0 ^ o1;
            float u = __uint_as_float((bits >> 9) | 0x3f800000u) - 1.0f;
            const float minv = 1e-6f, maxv = 1.0f - 1e-6f;
            u = fmaxf(minv, u * (maxv - minv) + minv);
            float g = -logf(-logf(u));
            float tau = fminf(fmaxf(expf(log_temp[0]), 0.1f), 5.0f);
            wts[lane] = (sc[lane] + g) / tau;
        }
        __syncwarp();
        if (lane == 0) {
            float mx = -1e30f;
            for (int k = 0; k < 8; k++) mx = fmaxf(mx, wts[k]);
            float s = 0.f;
            for (int k = 0; k < 8; k++) { float e = expf(wts[k] - mx); wts[k] = e; s += e; }
            float inv = 1.0f / s;
            for (int k = 0; k < 8; k++) wts[k] *= inv;
        }
    } else if (warp == 1) {
        if (lane < 16) {
            float s = 0.f;
            for (int m = 0; m < M_; m++) s += rule_mem[(b * M_ + m) * 16 + lane];
            rs[lane] = s * (1.0f / M_);
        }
        __syncwarp();
        for (int j = lane; j < 128; j += 32) {
            float a = br[j];
#pragma unroll
            for (int d = 0; d < 16; d++) a += rs[d] * Wr[d * 128 + j];
            rmod[j] = a;
        }
    }
    __syncthreads();
    if (warp == 0 && lane < 16) {
        float s = 0.f;
#pragma unroll
        for (int k = 0; k < 8; k++)
            s += wts[k] * sc[k] * (templates[k * 16 + lane] + rmod[k * 16 + lane]);
        combS[lane] = s;
    }
    __syncthreads();

    float a[16];
#pragma unroll
    for (int j = 0; j < 16; j++) a[j] = combS[j];

    // ---- pipelined tile loop: wait, compute in place, store, reload ----
#pragma unroll
    for (int t = 0; t < TILES_PER_BLOCK; t++) {
        const int bufi = t & 1;
        const int phase = t >> 1;                 // mbar phase parity
        const unsigned bufA = bufi ? smem_buf1 : smem_buf0;
        const unsigned barA = bufi ? smem_bar1 : smem_bar0;
        char* bufP = smt[bufi];

        // wait for this tile's TMA load
        asm volatile(
            "{\n\t.reg .pred P;\n"
            "W_%=:\n\t"
            "mbarrier.try_wait.parity.acquire.cta.shared::cta.b64 P, [%0], %1, 0x989680;\n\t"
            "@P bra D_%=;\n\t"
            "bra W_%=;\n"
            "D_%=:\n\t}"
            :: "r"(barA), "r"(phase) : "memory");

        // geometric product, 1 cell/thread, in place (same-thread slots)
        {
            float x[16];
#pragma unroll
            for (int q = 0; q < 4; q++) {
                unsigned off = (unsigned)tid * 64u + (unsigned)q * 16u;
                float4 v = *(const float4*)(bufP + sw128(off));
                x[q * 4 + 0] = v.x; x[q * 4 + 1] = v.y;
                x[q * 4 + 2] = v.z; x[q * 4 + 3] = v.w;
            }
            float y[16];
#pragma unroll
            for (int l = 0; l < 16; l++) {
                float s = 0.f;
#pragma unroll
                for (int j = 0; j < 16; j++) {
                    const float sgn = csign(j ^ l, j);   // compile-time constant
                    if (sgn > 0.5f)       s = fmaf(a[j ^ l],  x[j], s);
                    else if (sgn < -0.5f) s = fmaf(-a[j ^ l], x[j], s);
                }
                y[l] = s;
            }
#pragma unroll
            for (int q = 0; q < 4; q++) {
                unsigned off = (unsigned)tid * 64u + (unsigned)q * 16u;
                *(float4*)(bufP + sw128(off)) =
                    make_float4(y[q * 4 + 0], y[q * 4 + 1],
                                y[q * 4 + 2], y[q * 4 + 3]);
            }
        }

        asm volatile("fence.proxy.async.shared::cta;" ::: "memory");
        __syncthreads();

        if (tid == 0) {
            asm volatile(
                "cp.async.bulk.tensor.2d.global.shared::cta.tile.bulk_group "
                "[%0, {%1, %2}], [%3];"
                :: "l"(&tmap_out), "r"(0), "r"(rowBase + t * TILE_ROWS), "r"(bufA)
                : "memory");
            asm volatile("cp.async.bulk.commit_group;" ::: "memory");

            if (t + 2 < TILES_PER_BLOCK) {
                // free this buffer (TMA has read it), then reload with tile t+2
                asm volatile("cp.async.bulk.wait_group.read 0;" ::: "memory");
                asm volatile("mbarrier.arrive.expect_tx.shared.b64 _, [%0], %1;"
                             :: "r"(barA), "r"(TILE_BYTES) : "memory");
                asm volatile(
                    "cp.async.bulk.tensor.2d.shared::cta.global.tile.mbarrier::complete_tx::bytes "
                    "[%0], [%1, {%2, %3}], [%4];"
                    :: "r"(bufA), "l"(&tmap_in), "r"(0),
                       "r"(rowBase + (t + 2) * TILE_ROWS), "r"(barA)
                    : "memory");
            }
        }
    }

    // full drain before exit (round-12 lesson: .read-only exit regressed)
    if (tid == 0) {
        asm volatile("cp.async.bulk.wait_group 0;" ::: "memory");
    }
}

// ---------------------------------------------------------------------------
// Host: tensor map encode via driver entry point (no -lcuda needed)
// ---------------------------------------------------------------------------
typedef CUresult (*PFN_encodeTiled)(
    CUtensorMap*, CUtensorMapDataType, cuuint32_t, void*,
    const cuuint64_t*, const cuuint64_t*, const cuuint32_t*, const cuuint32_t*,
    CUtensorMapInterleave, CUtensorMapSwizzle, CUtensorMapL2promotion,
    CUtensorMapFloatOOBfill);

static void make_tmap(CUtensorMap* map, void* ptr) {
    static PFN_encodeTiled fn = nullptr;
    if (!fn) {
        cudaDriverEntryPointQueryResult qres;
        void* p = nullptr;
        cudaGetDriverEntryPoint("cuTensorMapEncodeTiled", &p,
                                cudaEnableDefault, &qres);
        fn = (PFN_encodeTiled)p;
    }
    cuuint64_t dims[2]    = {32, (cuuint64_t)TOTAL_ROWS};  // 32 f32 = 128B rows
    cuuint64_t strides[1] = {128};
    cuuint32_t box[2]     = {32, TILE_ROWS};
    cuuint32_t estr[2]    = {1, 1};
    fn(map, CU_TENSOR_MAP_DATA_TYPE_FLOAT32, 2, ptr, dims, strides, box, estr,
       CU_TENSOR_MAP_INTERLEAVE_NONE, CU_TENSOR_MAP_SWIZZLE_128B,
       CU_TENSOR_MAP_L2_PROMOTION_L2_128B, CU_TENSOR_MAP_FLOAT_OOB_FILL_NONE);
}

extern "C" void kernel_launch(void* const* d_in, const int* in_sizes, int n_in,
                              void* d_out, int out_size) {
    const float* cpu_state   = (const float*)d_in[0];
    const float* ctrl_cursor = (const float*)d_in[1];
    const float* rule_memory = (const float*)d_in[2];
    const float* templates   = (const float*)d_in[3];
    const float* W1          = (const float*)d_in[4];
    const float* b1          = (const float*)d_in[5];
    const float* W2          = (const float*)d_in[6];
    const float* b2          = (const float*)d_in[7];
    const float* Wr          = (const float*)d_in[8];
    const float* br          = (const float*)d_in[9];
    const float* log_temp    = (const float*)d_in[10];

    CUtensorMap tmap_in, tmap_out;
    make_tmap(&tmap_in, (void*)cpu_state);
    make_tmap(&tmap_out, d_out);

    dim3 gA(NBLK, B_);
    gss_reduce_kernel<<<gA, RED_THREADS>>>(cpu_state);

    gss_apply_kernel<<<APPLY_GRID, C_THREADS>>>(
        tmap_in, tmap_out, ctrl_cursor, rule_memory, templates,
        W1, b1, W2, b2, Wr, br, log_temp);
}